// round 2
// baseline (speedup 1.0000x reference)
#include <cuda_runtime.h>
#include <math.h>
#include <float.h>

#define B_ROWS 2048
#define D2 256
#define D 128
#define M_ITEMS 100000
#define SPLITS 16
#define TILE_R 64
#define TILE_T 128
#define KC 32
#define NTILES ((M_ITEMS + TILE_T - 1) / TILE_T)   /* 782 */
#define RB (B_ROWS / TILE_R)                       /* 32  */

/* ----- scratch (no allocations allowed) ----- */
__device__ float d_h[B_ROWS * D];
__device__ float d_scale[D];
__device__ float d_shift[D];
__device__ float d_partMax[B_ROWS * SPLITS];
__device__ int   d_partIdx[B_ROWS * SPLITS];
__device__ float d_sim[B_ROWS];

/* =====================  K1: h = x @ W + b  ===================== */
/* grid 256 blocks (8 rows each), 256 threads */
__global__ void k1_gemm_h(const float* __restrict__ x,
                          const float* __restrict__ W,
                          const float* __restrict__ bvec) {
    __shared__ float x_s[8][D2];
    const int tid = threadIdx.x;
    const int rbase = blockIdx.x * 8;

    /* stage 8 rows of x (8 x 256 floats) */
    #pragma unroll
    for (int i = 0; i < 2; ++i) {
        int li = tid + i * 256;          /* float4 index, 0..511 */
        int row = li >> 6;               /* 64 float4 per row    */
        int kv  = li & 63;
        float4 v = reinterpret_cast<const float4*>(x + (size_t)(rbase + row) * D2)[kv];
        x_s[row][kv * 4 + 0] = v.x;
        x_s[row][kv * 4 + 1] = v.y;
        x_s[row][kv * 4 + 2] = v.z;
        x_s[row][kv * 4 + 3] = v.w;
    }
    __syncthreads();

    const int jg  = tid & 31;            /* 32 column groups of 4 */
    const int row = tid >> 5;            /* 8 rows                */
    float4 acc = reinterpret_cast<const float4*>(bvec)[jg];
    const float4* W4 = reinterpret_cast<const float4*>(W);
    #pragma unroll 8
    for (int k = 0; k < D2; ++k) {
        float4 w = W4[k * 32 + jg];
        float xv = x_s[row][k];
        acc.x += xv * w.x; acc.y += xv * w.y;
        acc.z += xv * w.z; acc.w += xv * w.w;
    }
    reinterpret_cast<float4*>(d_h + (size_t)(rbase + row) * D)[jg] = acc;
}

/* ============  K2: per-column mean/var -> scale/shift  ============ */
/* grid 8 blocks (16 cols each), 256 threads (16 cols x 16 row-lanes) */
__global__ void k2_stats(const float* __restrict__ gamma,
                         const float* __restrict__ beta) {
    const int c   = threadIdx.x & 15;
    const int col = blockIdx.x * 16 + c;
    double s = 0.0, sq = 0.0;
    for (int i = (threadIdx.x >> 4); i < B_ROWS; i += 16) {
        float v = d_h[i * D + col];
        s += (double)v;
        sq += (double)v * (double)v;
    }
    __shared__ double rs[256], rq[256];
    rs[threadIdx.x] = s; rq[threadIdx.x] = sq;
    __syncthreads();
    for (int off = 128; off >= 16; off >>= 1) {
        if (threadIdx.x < off) {
            rs[threadIdx.x] += rs[threadIdx.x + off];
            rq[threadIdx.x] += rq[threadIdx.x + off];
        }
        __syncthreads();
    }
    if (threadIdx.x < 16) {
        double mu  = rs[threadIdx.x] / (double)B_ROWS;
        double var = rq[threadIdx.x] / (double)B_ROWS - mu * mu;
        float sc = gamma[col] * (float)(1.0 / sqrt(var + 1e-5));
        d_scale[col] = sc;
        d_shift[col] = beta[col] - (float)mu * sc;
    }
}

/* ===========  K3: fused (BN+leaky) @ items^T + argmax  =========== */
/* grid (32 row-blocks, 16 item-splits), 128 threads, 8x8 microtile  */
__global__ void __launch_bounds__(128, 4)
k3_score(const float* __restrict__ items) {
    __shared__ float uf_s[D][TILE_R];    /* [k][r]  32 KB */
    __shared__ float it_s[KC][TILE_T];   /* [k][t]  16 KB */

    const int tid   = threadIdx.x;
    const int rb    = blockIdx.x;
    const int split = blockIdx.y;
    const int rbase = rb * TILE_R;

    /* stage uf tile: load h, apply BN + leaky, store k-major */
    #pragma unroll
    for (int i = 0; i < 16; ++i) {
        int li  = tid + i * 128;         /* float4 index, 0..2047 */
        int row = li >> 5;               /* 32 float4 per row     */
        int kv  = li & 31;
        float4 h4 = reinterpret_cast<const float4*>(d_h + (size_t)(rbase + row) * D)[kv];
        int k0 = kv * 4;
        float v;
        v = h4.x * d_scale[k0 + 0] + d_shift[k0 + 0]; uf_s[k0 + 0][row] = (v >= 0.f) ? v : 0.01f * v;
        v = h4.y * d_scale[k0 + 1] + d_shift[k0 + 1]; uf_s[k0 + 1][row] = (v >= 0.f) ? v : 0.01f * v;
        v = h4.z * d_scale[k0 + 2] + d_shift[k0 + 2]; uf_s[k0 + 2][row] = (v >= 0.f) ? v : 0.01f * v;
        v = h4.w * d_scale[k0 + 3] + d_shift[k0 + 3]; uf_s[k0 + 3][row] = (v >= 0.f) ? v : 0.01f * v;
    }
    __syncthreads();

    const int tg = tid & 15;             /* item group: items tg + 16*jj */
    const int rg = tid >> 4;             /* row group: rows rg*8 .. +7   */
    const int r0 = rg * 8;

    float bmax[8];
    int   bidx[8];
    #pragma unroll
    for (int i = 0; i < 8; ++i) { bmax[i] = -FLT_MAX; bidx[i] = 0; }

    for (int tile = split; tile < NTILES; tile += SPLITS) {
        const int ibase = tile * TILE_T;
        float acc[8][8];
        #pragma unroll
        for (int ri = 0; ri < 8; ++ri)
            #pragma unroll
            for (int jj = 0; jj < 8; ++jj) acc[ri][jj] = 0.f;

        #pragma unroll
        for (int ks = 0; ks < D / KC; ++ks) {
            __syncthreads();             /* it_s reuse barrier */
            /* stage item slice: 128 items x 32 k, k-major */
            #pragma unroll
            for (int i = 0; i < 8; ++i) {
                int li = tid + i * 128;  /* float4 index, 0..1023 */
                int it = li >> 3;        /* 8 float4 per item     */
                int kv = li & 7;
                int gitem = ibase + it;
                if (gitem >= M_ITEMS) gitem = M_ITEMS - 1;
                float4 v = reinterpret_cast<const float4*>(items + (size_t)gitem * D + ks * KC)[kv];
                int k0 = kv * 4;
                it_s[k0 + 0][it] = v.x;
                it_s[k0 + 1][it] = v.y;
                it_s[k0 + 2][it] = v.z;
                it_s[k0 + 3][it] = v.w;
            }
            __syncthreads();

            #pragma unroll 8
            for (int kl = 0; kl < KC; ++kl) {
                const int k = ks * KC + kl;
                float a[8];
                float4 a0 = *reinterpret_cast<const float4*>(&uf_s[k][r0]);
                float4 a1 = *reinterpret_cast<const float4*>(&uf_s[k][r0 + 4]);
                a[0] = a0.x; a[1] = a0.y; a[2] = a0.z; a[3] = a0.w;
                a[4] = a1.x; a[5] = a1.y; a[6] = a1.z; a[7] = a1.w;
                float b[8];
                #pragma unroll
                for (int jj = 0; jj < 8; ++jj) b[jj] = it_s[kl][tg + 16 * jj];
                #pragma unroll
                for (int ri = 0; ri < 8; ++ri)
                    #pragma unroll
                    for (int jj = 0; jj < 8; ++jj)
                        acc[ri][jj] += a[ri] * b[jj];
            }
        }

        /* argmax epilogue for this tile */
        #pragma unroll
        for (int jj = 0; jj < 8; ++jj) {
            int j = ibase + tg + 16 * jj;
            if (j < M_ITEMS) {
                #pragma unroll
                for (int ri = 0; ri < 8; ++ri) {
                    if (acc[ri][jj] > bmax[ri]) { bmax[ri] = acc[ri][jj]; bidx[ri] = j; }
                }
            }
        }
    }

    /* cross-thread (tg) reduction via smem reuse */
    __syncthreads();
    float* redM = &it_s[0][0];                       /* 64*16 floats */
    int*   redI = reinterpret_cast<int*>(&uf_s[0][0]);
    #pragma unroll
    for (int ri = 0; ri < 8; ++ri) {
        redM[(r0 + ri) * 16 + tg] = bmax[ri];
        redI[(r0 + ri) * 16 + tg] = bidx[ri];
    }
    __syncthreads();
    if (tid < 64) {
        float m = redM[tid * 16];
        int  ix = redI[tid * 16];
        #pragma unroll
        for (int t = 1; t < 16; ++t) {
            float om = redM[tid * 16 + t];
            int   oi = redI[tid * 16 + t];
            if (om > m || (om == m && oi < ix)) { m = om; ix = oi; }
        }
        d_partMax[(rbase + tid) * SPLITS + split] = m;
        d_partIdx[(rbase + tid) * SPLITS + split] = ix;
    }
}

/* =========  K4: combine splits, cosine sim, write top1  ========= */
/* grid 256 blocks x 256 threads = one warp per row                 */
/* NOTE: user_item_id is int32 on device (JAX x64 disabled demotes  */
/* jnp.int64 -> int32). Reading it as int64 was the R1 OOB crash.   */
__global__ void k4_combine(const float* __restrict__ items,
                           const int* __restrict__ uid,
                           float* __restrict__ out) {
    const int warp = threadIdx.x >> 5;
    const int lane = threadIdx.x & 31;
    const int row  = blockIdx.x * 8 + warp;

    float m = -FLT_MAX;
    int  ix = 0x7fffffff;
    if (lane < SPLITS) {
        m  = d_partMax[row * SPLITS + lane];
        ix = d_partIdx[row * SPLITS + lane];
    }
    #pragma unroll
    for (int off = 16; off; off >>= 1) {
        float om = __shfl_down_sync(0xffffffffu, m, off);
        int   oi = __shfl_down_sync(0xffffffffu, ix, off);
        if (om > m || (om == m && oi < ix)) { m = om; ix = oi; }
    }
    ix = __shfl_sync(0xffffffffu, ix, 0);

    const int orig = uid[2 * row + 1];
    float4 a4 = reinterpret_cast<const float4*>(items + (size_t)orig * D)[lane];
    float4 c4 = reinterpret_cast<const float4*>(items + (size_t)ix * D)[lane];
    float aa = a4.x * a4.x + a4.y * a4.y + a4.z * a4.z + a4.w * a4.w;
    float cc = c4.x * c4.x + c4.y * c4.y + c4.z * c4.z + c4.w * c4.w;
    float ac = a4.x * c4.x + a4.y * c4.y + a4.z * c4.z + a4.w * c4.w;
    #pragma unroll
    for (int off = 16; off; off >>= 1) {
        aa += __shfl_xor_sync(0xffffffffu, aa, off);
        cc += __shfl_xor_sync(0xffffffffu, cc, off);
        ac += __shfl_xor_sync(0xffffffffu, ac, off);
    }
    if (lane == 0) {
        float na = fmaxf(sqrtf(aa), 1e-6f);
        float nc = fmaxf(sqrtf(cc), 1e-6f);
        float sim = ac / (na * nc);
        float s01 = (sim + 1.f) * 0.5f;
        d_sim[row] = s01;
        out[row]   = (float)ix;
    }
}

/* =========  K5: deterministic means -> loss, mean_sim  ========= */
__global__ void k5_final(float* __restrict__ out) {
    __shared__ float s1[1024], s2[1024];
    const int tid = threadIdx.x;
    float a = d_sim[tid];
    float b = d_sim[tid + 1024];
    s1[tid] = a + b;
    s2[tid] = fmaxf(a - 0.5f, 0.f) + fmaxf(b - 0.5f, 0.f);
    __syncthreads();
    for (int off = 512; off; off >>= 1) {
        if (tid < off) { s1[tid] += s1[tid + off]; s2[tid] += s2[tid + off]; }
        __syncthreads();
    }
    if (tid == 0) {
        out[B_ROWS]     = s2[0] / (float)B_ROWS;  /* similarity_loss */
        out[B_ROWS + 1] = s1[0] / (float)B_ROWS;  /* mean(sim)       */
    }
}

extern "C" void kernel_launch(void* const* d_in, const int* in_sizes, int n_in,
                              void* d_out, int out_size) {
    const float* item_feature = (const float*)d_in[0];
    const float* all_items    = (const float*)d_in[1];
    const int*   uid          = (const int*)d_in[2];
    const float* W            = (const float*)d_in[3];
    const float* bvec         = (const float*)d_in[4];
    const float* gamma        = (const float*)d_in[5];
    const float* beta         = (const float*)d_in[6];
    float* out = (float*)d_out;

    k1_gemm_h<<<B_ROWS / 8, 256>>>(item_feature, W, bvec);
    k2_stats<<<8, 256>>>(gamma, beta);
    dim3 g3(RB, SPLITS);
    k3_score<<<g3, 128>>>(all_items);
    k4_combine<<<B_ROWS / 8, 256>>>(all_items, uid, out);
    k5_final<<<1, 1024>>>(out);
}